// round 16
// baseline (speedup 1.0000x reference)
#include <cuda_runtime.h>
#include <cuda_fp16.h>
#include <float.h>
#include <limits.h>

#define FULL 0xFFFFFFFFu

static constexpr int B = 4;
static constexpr int N = 8192;
static constexpr int M = 2048;
static constexpr int F = 256;
static constexpr int K = 16;
static constexpr int OUTC = 3 + F;     // 259
static constexpr int HB = 256;         // point x-buckets
static constexpr int QB = 128;         // query x-buckets
static constexpr int NC = 4;           // chunks of 2048 sorted points
static constexpr float SLACK = 1e-3f;  // prune slack (only loosens pruning)

static constexpr int KNNB = (B * M) / 16;              // 512 knn blocks
static constexpr int TRB  = B * (F / 32) * (N / 128);  // 2048 transpose tiles

// ---------------- device scratch (no allocation allowed) ----------------
__device__ float4 g_spts[B * N];      // sorted by x: (x,y,z,p2)  p2 = R1 fmaf chain
__device__ int    g_sidx[B * N];      // sorted pos -> original point index
__device__ int    g_qord[B * M];      // sorted query order -> original m
__device__ int    g_off [B * HB];     // point-bucket END offsets (for home lookup)
__device__ float  g_cmin[B * NC];     // per-chunk exact x min
__device__ float  g_cmax[B * NC];     // per-chunk exact x max
__device__ __half g_featT[(size_t)B * N * F];  // 16MB transposed features (B,N,F)
__device__ int    g_idx[B * M * K];
__device__ float  g_w  [B * M * K];

__device__ __forceinline__ int clampi(int v, int lo, int hi) {
    return v < lo ? lo : (v > hi ? hi : v);
}
__device__ __forceinline__ unsigned encf(float f) {
    unsigned u = __float_as_uint(f);
    return (u & 0x80000000u) ? ~u : (u | 0x80000000u);
}
__device__ __forceinline__ float decf(unsigned e) {
    unsigned u = (e & 0x80000000u) ? (e ^ 0x80000000u) : ~e;
    return __uint_as_float(u);
}

// ---------------- preprocessing: ONE kernel, one block per batch -----------
// smem histogram -> smem scan -> scatter (sorted points + query order) ->
// per-chunk x min/max (encoded atomics).
__global__ __launch_bounds__(1024) void prep_kernel(
    const float* __restrict__ pc, const float* __restrict__ qc)
{
    __shared__ int hoff[HB];
    __shared__ int qoff[QB];
    __shared__ unsigned cmnE[NC], cmxE[NC];

    const int b   = blockIdx.x;
    const int tid = threadIdx.x;
    const int lane = tid & 31;
    const int w    = tid >> 5;

    if (tid < HB) hoff[tid] = 0;
    if (tid < QB) qoff[tid] = 0;
    if (tid < NC) { cmnE[tid] = 0xFFFFFFFFu; cmxE[tid] = 0u; }
    __syncthreads();

    const float* pcb = pc + (size_t)b * 3 * N;
    const float* qcb = qc + (size_t)b * 3 * M;

    for (int n = tid; n < N; n += 1024) {
        float x = pcb[n];
        int bp = clampi((int)((x + 4.0f) * 32.0f), 0, HB - 1);
        atomicAdd(&hoff[bp], 1);
    }
    for (int m = tid; m < M; m += 1024) {
        float x = qcb[m];
        int bq = clampi((int)((x + 4.0f) * 16.0f), 0, QB - 1);
        atomicAdd(&qoff[bq], 1);
    }
    __syncthreads();

    if (w == 0) {                     // scan point hist: 256 vals, 8/lane
        int loc[8], tot = 0;
        #pragma unroll
        for (int i = 0; i < 8; ++i) { loc[i] = tot; tot += hoff[lane * 8 + i]; }
        int inc = tot;
        #pragma unroll
        for (int o = 1; o < 32; o <<= 1) {
            int t = __shfl_up_sync(FULL, inc, o);
            if (lane >= o) inc += t;
        }
        int ex = inc - tot;
        #pragma unroll
        for (int i = 0; i < 8; ++i) hoff[lane * 8 + i] = ex + loc[i];
    } else if (w == 1) {              // scan query hist: 128 vals, 4/lane
        int loc[4], tot = 0;
        #pragma unroll
        for (int i = 0; i < 4; ++i) { loc[i] = tot; tot += qoff[lane * 4 + i]; }
        int inc = tot;
        #pragma unroll
        for (int o = 1; o < 32; o <<= 1) {
            int t = __shfl_up_sync(FULL, inc, o);
            if (lane >= o) inc += t;
        }
        int ex = inc - tot;
        #pragma unroll
        for (int i = 0; i < 4; ++i) qoff[lane * 4 + i] = ex + loc[i];
    }
    __syncthreads();

    for (int n = tid; n < N; n += 1024) {
        float x = pcb[n], y = pcb[N + n], z = pcb[2 * N + n];
        int bp = clampi((int)((x + 4.0f) * 32.0f), 0, HB - 1);
        int pos = atomicAdd(&hoff[bp], 1);
        // p2 with EXACT R1 fmaf chain (key bits must match R1's)
        g_spts[(size_t)b * N + pos] = make_float4(x, y, z, fmaf(x, x, fmaf(y, y, z * z)));
        g_sidx[(size_t)b * N + pos] = n;
        int c = pos >> 11;            // 2048 per chunk
        unsigned e = encf(x);
        atomicMin(&cmnE[c], e);
        atomicMax(&cmxE[c], e);
    }
    for (int m = tid; m < M; m += 1024) {
        float x = qcb[m];
        int bq = clampi((int)((x + 4.0f) * 16.0f), 0, QB - 1);
        int pos = atomicAdd(&qoff[bq], 1);
        g_qord[b * M + pos] = m;
    }
    __syncthreads();

    if (tid < HB) g_off[b * HB + tid] = hoff[tid];   // end offsets
    if (tid < NC) {
        g_cmin[b * NC + tid] = decf(cmnE[tid]);
        g_cmax[b * NC + tid] = decf(cmxE[tid]);
    }
}

// ---------------------------------------------------------------------------
// Fused kernel, 512-thread blocks.
//   blocks [0, 512):     KNN — R9 engine (16 warps, warp/query, block-staged
//                        32KB chunks, ballot + warp-sorted insert) over
//                        x-sorted points, expanding outward from the block's
//                        home chunk with envelope pruning. Selection uses
//                        (key, orig-index) ordering — proven bit-exact vs
//                        jax.lax.top_k in R10.
//   blocks [512, 2560):  transpose (B,F,N)->(B,N,F) fp16 store (R14-proven).
// ---------------------------------------------------------------------------
__global__ __launch_bounds__(512) void fused_knn_transpose(
    const float* __restrict__ pc,
    const float* __restrict__ qc,
    const float* __restrict__ temperature,
    const float* __restrict__ feat,
    float* __restrict__ out)
{
    __shared__ __align__(16) unsigned char smem_raw[40960];  // 32KB pts + 8KB org
    __shared__ int sHome;

    if (blockIdx.x < KNNB) {
        // ===================== KNN =====================
        float4* s_pts = (float4*)smem_raw;               // [2048]
        int*    s_org = (int*)(smem_raw + 32768);        // [2048]

        const int tid  = threadIdx.x;
        const int lane = tid & 31;
        const int wid  = tid >> 5;
        const int b    = blockIdx.x >> 7;                // 128 blocks per batch
        const int qp   = ((blockIdx.x & 127) << 4) + wid;
        const int m    = g_qord[b * M + qp];

        const float* pcb = pc + (size_t)b * 3 * N;

        const float qx = qc[((size_t)b * 3 + 0) * M + m];
        const float qy = qc[((size_t)b * 3 + 1) * M + m];
        const float qz = qc[((size_t)b * 3 + 2) * M + m];
        const float q2 = fmaf(qx, qx, fmaf(qy, qy, qz * qz));
        const float ax = -2.0f * qx, ay = -2.0f * qy, az = -2.0f * qz;

        // chunk envelopes (4 values each — registers)
        float cmaxLE[NC], cminRE[NC];
        {
            float c0 = g_cmax[b * NC + 0], c1 = g_cmax[b * NC + 1],
                  c2 = g_cmax[b * NC + 2], c3 = g_cmax[b * NC + 3];
            cmaxLE[0] = c0;
            cmaxLE[1] = fmaxf(cmaxLE[0], c1);
            cmaxLE[2] = fmaxf(cmaxLE[1], c2);
            cmaxLE[3] = fmaxf(cmaxLE[2], c3);
            float n0 = g_cmin[b * NC + 0], n1 = g_cmin[b * NC + 1],
                  n2 = g_cmin[b * NC + 2], n3 = g_cmin[b * NC + 3];
            cminRE[3] = n3;
            cminRE[2] = fminf(cminRE[3], n2);
            cminRE[1] = fminf(cminRE[2], n1);
            cminRE[0] = fminf(cminRE[1], n0);
        }

        // home chunk: sorted position of this query's x bucket
        int bq = clampi((int)((qx + 4.0f) * 32.0f), 0, HB - 1);
        int myHome = clampi(g_off[b * HB + bq] >> 11, 0, NC - 1);
        if (tid == 0) sHome = myHome;
        __syncthreads();
        const int home = sHome;

        float kd  = FLT_MAX;   // warp-sorted list by (key, orig idx); lane i = i-th best
        int   ki  = INT_MAX;   // original point index
        float thr = FLT_MAX;   // 16th-best key
        int   thrI = INT_MAX;  // its original index
        bool doneL = false, doneR = false;
        int lo = home, hi = home - 1;   // scanned/covered range (initially empty)

        for (int s = 0; s < 7; ++s) {
            int d = (s + 1) >> 1;
            int c = (s == 0) ? home : ((s & 1) ? home + d : home - d);
            if (c < 0 || c >= NC) continue;

            bool skip = (c < myHome && doneL) || (c > myHome && doneR);
            int want = __syncthreads_or(skip ? 0 : 1);
            if (want) {
                __syncthreads();   // all warps done reading previous chunk
                for (int i = tid; i < 2048; i += 512) {
                    int sp = c * 2048 + i;
                    s_pts[i] = g_spts[(size_t)b * N + sp];
                    s_org[i] = g_sidx[(size_t)b * N + sp];
                }
                __syncthreads();

                if (!skip) {
                    #pragma unroll 4
                    for (int t = 0; t < 64; ++t) {
                        float4 p = s_pts[t * 32 + lane];
                        int   org = s_org[t * 32 + lane];
                        float sc = fmaf(ax, p.x, p.w);   // EXACT R1 key chain
                        sc = fmaf(ay, p.y, sc);
                        sc = fmaf(az, p.z, sc);
                        bool acc = (sc < thr) || (sc == thr && org < thrI);
                        unsigned mask = __ballot_sync(FULL, acc);
                        if (mask) {
                            do {
                                int src = __ffs(mask) - 1;
                                mask &= mask - 1;
                                float cd = __shfl_sync(FULL, sc, src);
                                int   co = __shfl_sync(FULL, org, src);
                                bool better = (kd < cd) || (kd == cd && ki < co);
                                int pos = __popc(__ballot_sync(FULL, better));
                                float ud = __shfl_up_sync(FULL, kd, 1);
                                int   uo = __shfl_up_sync(FULL, ki, 1);
                                if (lane >= pos) {
                                    kd = (lane == pos) ? cd : ud;
                                    ki = (lane == pos) ? co : uo;
                                }
                            } while (mask);
                            thr  = __shfl_sync(FULL, kd, 15);
                            thrI = __shfl_sync(FULL, ki, 15);
                        }
                    }
                }
            }
            if (c < lo) lo = c;
            if (c > hi) hi = c;

            // update prune flags (thr only tightens -> latched flags stay valid)
            float bound = thr + q2 + SLACK;
            if (!doneL) {
                int nL = lo - 1;
                if (nL < 0) doneL = true;
                else {
                    float g = qx - cmaxLE[nL];
                    if (g > 0.0f && g * g >= bound) doneL = true;
                }
            }
            if (!doneR) {
                int nR = hi + 1;
                if (nR >= NC) doneR = true;
                else {
                    float g = cminRE[nR] - qx;
                    if (g > 0.0f && g * g >= bound) doneR = true;
                }
            }
            if (__syncthreads_and((doneL && doneR) ? 1 : 0)) break;
        }

        // softmax over the 16 best (shift-invariant in s) — R1 formula
        float tv = *temperature;
        float sigma = fmaxf(tv * tv, 1e-4f);
        float inv_sigma = 1.0f / sigma;
        float s0 = __shfl_sync(FULL, kd, 0);
        float ev = (lane < K) ? __expf((s0 - kd) * inv_sigma) : 0.0f;
        float sum = ev;
        #pragma unroll
        for (int o = 16; o; o >>= 1) sum += __shfl_xor_sync(FULL, sum, o);
        float w = ev / sum;

        int kis = (lane < K) ? ki : 0;   // guard OOB for unused lanes
        float px = pcb[kis];
        float py = pcb[N + kis];
        float pz = pcb[2 * N + kis];
        float sx = w * px, sy = w * py, sz = w * pz;
        #pragma unroll
        for (int o = 16; o; o >>= 1) {
            sx += __shfl_xor_sync(FULL, sx, o);
            sy += __shfl_xor_sync(FULL, sy, o);
            sz += __shfl_xor_sync(FULL, sz, o);
        }
        if (lane == 0) {
            out[((size_t)b * OUTC + 0) * M + m] = sx;
            out[((size_t)b * OUTC + 1) * M + m] = sy;
            out[((size_t)b * OUTC + 2) * M + m] = sz;
        }
        if (lane < K) {
            size_t gq = (size_t)b * M + m;
            g_idx[gq * K + lane] = ki;
            g_w[gq * K + lane]   = w;
        }
    } else {
        // ===================== transpose (fp16 store, R14-proven) ==========
        float (*tile)[129] = (float (*)[129])smem_raw;   // 16512B

        int t  = blockIdx.x - KNNB;
        int b  = t >> 9;
        int r  = t & 511;
        int fb = r >> 6;
        int nb = r & 63;

        int tx = threadIdx.x & 127;
        int ty = threadIdx.x >> 7;
        const float* src = feat + ((size_t)b * F + fb * 32) * N + nb * 128;
        #pragma unroll
        for (int j = ty; j < 32; j += 4)
            tile[j][tx] = src[(size_t)j * N + tx];
        __syncthreads();

        int cx = threadIdx.x & 31;
        int cy = threadIdx.x >> 5;
        __half* dst = g_featT + ((size_t)b * N + nb * 128) * F + fb * 32;
        #pragma unroll
        for (int j = cy; j < 128; j += 16)
            dst[(size_t)j * F + cx] = __float2half(tile[cx][j]);
    }
}

// ---------------------------------------------------------------------------
// Feature propagation (R14-proven, byte-identical): 1024 threads = 32 warps =
// 16 queries, 2 warps/query; fp16 gathers (8B/lane/neighbor), fp32 accum.
// ---------------------------------------------------------------------------
__global__ __launch_bounds__(1024) void feat_kernel(float* __restrict__ out)
{
    __shared__ float so[16][260];

    const int lane   = threadIdx.x & 31;
    const int wid    = threadIdx.x >> 5;
    const int qlocal = wid >> 1;
    const int half   = wid & 1;
    const int b      = blockIdx.x >> 7;
    const int m0     = (blockIdx.x & 127) * 16;
    const int m      = m0 + qlocal;
    const size_t gq  = (size_t)b * M + m;

    int   iv = 0;
    float wv = 0.0f;
    if (lane < K) {
        iv = g_idx[gq * K + lane];
        wv = g_w[gq * K + lane];
    }

    float4 acc = make_float4(0.f, 0.f, 0.f, 0.f);
    #pragma unroll
    for (int j = 0; j < K; ++j) {
        float wj = __shfl_sync(FULL, wv, j);
        int   ij = __shfl_sync(FULL, iv, j);
        const __half* basep =
            g_featT + ((size_t)b * N + ij) * F + half * 128;
        uint2 raw = *(const uint2*)(basep + lane * 4);
        __half2 h01 = *reinterpret_cast<__half2*>(&raw.x);
        __half2 h23 = *reinterpret_cast<__half2*>(&raw.y);
        float2 f01 = __half22float2(h01);
        float2 f23 = __half22float2(h23);
        acc.x = fmaf(wj, f01.x, acc.x);
        acc.y = fmaf(wj, f01.y, acc.y);
        acc.z = fmaf(wj, f23.x, acc.z);
        acc.w = fmaf(wj, f23.y, acc.w);
    }

    *(float4*)&so[qlocal][half * 128 + 4 * lane] = acc;
    __syncthreads();

    #pragma unroll
    for (int r = 0; r < 4; ++r) {
        int f  = wid * 8 + r * 2 + (lane >> 4);
        int ml = lane & 15;
        out[((size_t)b * OUTC + 3 + f) * M + m0 + ml] = so[ml][f];
    }
}

// ---------------------------------------------------------------------------
extern "C" void kernel_launch(void* const* d_in, const int* in_sizes, int n_in,
                              void* d_out, int out_size)
{
    const float* pc   = (const float*)d_in[0];  // point_cloud (B,3,N)
    const float* qc   = (const float*)d_in[1];  // query_cloud (B,3,M)
    const float* feat = (const float*)d_in[2];  // point_features (B,F,N)
    const float* temp = (const float*)d_in[3];  // temperature scalar
    float* out = (float*)d_out;

    prep_kernel<<<B, 1024>>>(pc, qc);
    fused_knn_transpose<<<KNNB + TRB, 512>>>(pc, qc, temp, feat, out);
    feat_kernel<<<(B * M) / 16, 1024>>>(out);
}

// round 17
// speedup vs baseline: 1.6707x; 1.6707x over previous
#include <cuda_runtime.h>
#include <cuda_fp16.h>
#include <float.h>

#define FULL 0xFFFFFFFFu

static constexpr int B = 4;
static constexpr int N = 8192;
static constexpr int M = 2048;
static constexpr int F = 256;
static constexpr int K = 16;
static constexpr int OUTC = 3 + F;  // 259

static constexpr int KNNB = (B * M) / 16;              // 512 knn blocks
static constexpr int TRB  = B * (F / 32) * (N / 128);  // 2048 transpose tiles

// Scratch (device globals — no allocation allowed)
__device__ __half g_featT[(size_t)B * N * F];  // 16MB transposed features (B,N,F) fp16
__device__ int    g_idx[(size_t)B * M * K];
__device__ float  g_w[(size_t)B * M * K];

// ---------------------------------------------------------------------------
// Fused kernel (R14-proven): 512-thread blocks, pinned to 4 blocks/SM
// (guarantees <=32 regs -> 64 warps/SM, the measured optimum).
//   blocks [0, 512):     KNN — warp per query, brute-force scan of all 8192
//                        points in original order, key s = |p|^2 - 2 q.p,
//                        warp-sorted top-16 with lazy 16th-best threshold.
//   blocks [512, 2560):  feature transpose (B,F,N)->(B,N,F), fp32->fp16 on
//                        store — co-resident DRAM streaming overlapped with
//                        the smem/issue-bound KNN.
// ---------------------------------------------------------------------------
__global__ __launch_bounds__(512, 4) void fused_knn_transpose(
    const float* __restrict__ pc,     // (B,3,N)
    const float* __restrict__ qc,     // (B,3,M)
    const float* __restrict__ temperature,
    const float* __restrict__ feat,   // (B,F,N)
    float* __restrict__ out)          // (B,259,M)
{
    __shared__ __align__(16) unsigned char smem_raw[32768];

    if (blockIdx.x < KNNB) {
        // ===================== KNN (R9/R14-exact) =====================
        float4* s_pts = (float4*)smem_raw;    // 2048 * 16B = 32KB

        const int tid  = threadIdx.x;
        const int lane = tid & 31;
        const int wid  = tid >> 5;
        const int b    = blockIdx.x >> 7;              // 128 blocks per batch
        const int m    = ((blockIdx.x & 127) << 4) + wid;

        const float* pcb = pc + (size_t)b * 3 * N;

        const float qx = qc[((size_t)b * 3 + 0) * M + m];
        const float qy = qc[((size_t)b * 3 + 1) * M + m];
        const float qz = qc[((size_t)b * 3 + 2) * M + m];
        const float ax = -2.0f * qx, ay = -2.0f * qy, az = -2.0f * qz;

        float kd = FLT_MAX;   // warp-sorted list: lane i = i-th smallest
        int   ki = 0;
        float thr = FLT_MAX;  // lazy copy of element 15 (16th smallest)

        for (int c = 0; c < 4; ++c) {
            __syncthreads();
            for (int i = tid; i < 2048; i += 512) {
                int n = c * 2048 + i;
                float x = pcb[n];
                float y = pcb[N + n];
                float z = pcb[2 * N + n];
                s_pts[i] = make_float4(x, y, z, fmaf(x, x, fmaf(y, y, z * z)));
            }
            __syncthreads();

            #pragma unroll 4
            for (int t = 0; t < 64; ++t) {
                float4 p = s_pts[t * 32 + lane];
                float s = fmaf(ax, p.x, p.w);
                s = fmaf(ay, p.y, s);
                s = fmaf(az, p.z, s);
                unsigned mask = __ballot_sync(FULL, s < thr);
                if (mask) {
                    int nbase = c * 2048 + t * 32;
                    do {
                        int src = __ffs(mask) - 1;
                        mask &= mask - 1;
                        float cd = __shfl_sync(FULL, s, src);
                        int   cn = nbase + src;
                        int pos = __popc(__ballot_sync(FULL, kd < cd));
                        float ud = __shfl_up_sync(FULL, kd, 1);
                        int   ui = __shfl_up_sync(FULL, ki, 1);
                        if (lane >= pos) {
                            kd = (lane == pos) ? cd : ud;
                            ki = (lane == pos) ? cn : ui;
                        }
                    } while (mask);
                    thr = __shfl_sync(FULL, kd, 15);
                }
            }
        }

        // softmax over the 16 smallest (shift-invariant in s)
        float tv = *temperature;
        float sigma = fmaxf(tv * tv, 1e-4f);
        float inv_sigma = 1.0f / sigma;
        float s0 = __shfl_sync(FULL, kd, 0);
        float ev = (lane < K) ? __expf((s0 - kd) * inv_sigma) : 0.0f;
        float sum = ev;
        #pragma unroll
        for (int o = 16; o; o >>= 1) sum += __shfl_xor_sync(FULL, sum, o);
        float w = ev / sum;

        // projected points: sum_k w_k * p_k (lanes >= 16 contribute w = 0)
        float px = pcb[ki];
        float py = pcb[N + ki];
        float pz = pcb[2 * N + ki];
        float sx = w * px, sy = w * py, sz = w * pz;
        #pragma unroll
        for (int o = 16; o; o >>= 1) {
            sx += __shfl_xor_sync(FULL, sx, o);
            sy += __shfl_xor_sync(FULL, sy, o);
            sz += __shfl_xor_sync(FULL, sz, o);
        }
        if (lane == 0) {
            out[((size_t)b * OUTC + 0) * M + m] = sx;
            out[((size_t)b * OUTC + 1) * M + m] = sy;
            out[((size_t)b * OUTC + 2) * M + m] = sz;
        }
        if (lane < K) {
            size_t gq = (size_t)b * M + m;
            g_idx[gq * K + lane] = ki;
            g_w[gq * K + lane]   = w;
        }
    } else {
        // ===================== transpose (fp16 store, R14-proven) ==========
        // (B,F,N) -> (B,N,F); tile = 32 f x 128 n per block
        float (*tile)[129] = (float (*)[129])smem_raw;   // 32*129*4 = 16512B

        int t  = blockIdx.x - KNNB;         // 0..2047
        int b  = t >> 9;                    // 512 tiles per batch
        int r  = t & 511;
        int fb = r >> 6;                    // 0..7  (f block of 32)
        int nb = r & 63;                    // 0..63 (n block of 128)

        int tx = threadIdx.x & 127;         // n within tile
        int ty = threadIdx.x >> 7;          // 0..3
        const float* src = feat + ((size_t)b * F + fb * 32) * N + nb * 128;
        #pragma unroll
        for (int j = ty; j < 32; j += 4)
            tile[j][tx] = src[(size_t)j * N + tx];
        __syncthreads();

        int cx = threadIdx.x & 31;          // f within tile
        int cy = threadIdx.x >> 5;          // 0..15
        __half* dst = g_featT + ((size_t)b * N + nb * 128) * F + fb * 32;
        #pragma unroll
        for (int j = cy; j < 128; j += 16)
            dst[(size_t)j * F + cx] = __float2half(tile[cx][j]);
    }
}

// ---------------------------------------------------------------------------
// Feature propagation (R14-proven): 1024 threads = 32 warps = 16 queries,
// 2 warps/query; fp16 gathers (8B/lane/neighbor), fp32 accumulation.
// Pinned to 2 blocks/SM (guarantees <=32 regs, the measured optimum).
// ---------------------------------------------------------------------------
__global__ __launch_bounds__(1024, 2) void feat_kernel(float* __restrict__ out)
{
    __shared__ float so[16][260];

    const int lane   = threadIdx.x & 31;
    const int wid    = threadIdx.x >> 5;       // 0..31
    const int qlocal = wid >> 1;               // 0..15
    const int half   = wid & 1;                // 0/1 -> 128 features each
    const int b      = blockIdx.x >> 7;        // 128 blocks per batch
    const int m0     = (blockIdx.x & 127) * 16;
    const int m      = m0 + qlocal;
    const size_t gq  = (size_t)b * M + m;

    int   iv = 0;
    float wv = 0.0f;
    if (lane < K) {
        iv = g_idx[gq * K + lane];
        wv = g_w[gq * K + lane];
    }

    float4 acc = make_float4(0.f, 0.f, 0.f, 0.f);
    #pragma unroll
    for (int j = 0; j < K; ++j) {
        float wj = __shfl_sync(FULL, wv, j);
        int   ij = __shfl_sync(FULL, iv, j);
        const __half* basep =
            g_featT + ((size_t)b * N + ij) * F + half * 128;
        uint2 raw = *(const uint2*)(basep + lane * 4);   // 4 halves, 8B aligned
        __half2 h01 = *reinterpret_cast<__half2*>(&raw.x);
        __half2 h23 = *reinterpret_cast<__half2*>(&raw.y);
        float2 f01 = __half22float2(h01);
        float2 f23 = __half22float2(h23);
        acc.x = fmaf(wj, f01.x, acc.x);
        acc.y = fmaf(wj, f01.y, acc.y);
        acc.z = fmaf(wj, f23.x, acc.z);
        acc.w = fmaf(wj, f23.y, acc.w);
    }

    *(float4*)&so[qlocal][half * 128 + 4 * lane] = acc;
    __syncthreads();

    // warp wid writes f rows [wid*8, wid*8+8); lanes: 2 f x 16 mLocal
    #pragma unroll
    for (int r = 0; r < 4; ++r) {
        int f  = wid * 8 + r * 2 + (lane >> 4);
        int ml = lane & 15;
        out[((size_t)b * OUTC + 3 + f) * M + m0 + ml] = so[ml][f];
    }
}

// ---------------------------------------------------------------------------
extern "C" void kernel_launch(void* const* d_in, const int* in_sizes, int n_in,
                              void* d_out, int out_size)
{
    const float* pc   = (const float*)d_in[0];  // point_cloud (B,3,N)
    const float* qc   = (const float*)d_in[1];  // query_cloud (B,3,M)
    const float* feat = (const float*)d_in[2];  // point_features (B,F,N)
    const float* temp = (const float*)d_in[3];  // temperature scalar
    float* out = (float*)d_out;

    fused_knn_transpose<<<KNNB + TRB, 512>>>(pc, qc, temp, feat, out);
    feat_kernel<<<(B * M) / 16, 1024>>>(out);
}